// round 17
// baseline (speedup 1.0000x reference)
#include <cuda_runtime.h>
#include <cstdint>
#include <math.h>

#define Bn   2
#define Sn   2048
#define Dn   512
#define Hn   8
#define DHn  64
#define HIDn 2048
#define TD3  1536
#define NROW (Bn*Sn)   /* 4096 */

// ---------------------------------------------------------------------------
// Scratch (static device globals — no runtime allocation)
// ---------------------------------------------------------------------------
__device__ float g_kqv[Bn*Sn*TD3];      // 25 MB  [B,S,3D] (k | q | v)
__device__ float g_ctx[Bn*Sn*Dn];       //  8 MB
__device__ float g_attnout[Bn*Sn*Dn];   //  8 MB
__device__ float g_h[Bn*Sn*Dn];         //  8 MB
__device__ float g_ff[Bn*Sn*Dn];        //  8 MB
__device__ float g_fc1[Bn*Sn*HIDn];     // 33 MB

__device__ __forceinline__ float gelu_exact(float x) {
    return 0.5f * x * (1.0f + erff(x * 0.70710678118654752f));
}

// TF32 tensor cores round FP32 inputs internally — feed raw f32 bits.
__device__ __forceinline__ void mma_tf32(float acc[4], const unsigned int a[4],
                                         const unsigned int b[2]) {
    asm volatile(
        "mma.sync.aligned.m16n8k8.row.col.f32.tf32.tf32.f32 "
        "{%0,%1,%2,%3}, {%4,%5,%6,%7}, {%8,%9}, {%0,%1,%2,%3};"
        : "+f"(acc[0]), "+f"(acc[1]), "+f"(acc[2]), "+f"(acc[3])
        : "r"(a[0]), "r"(a[1]), "r"(a[2]), "r"(a[3]), "r"(b[0]), "r"(b[1]));
}

__device__ __forceinline__ void cp_async16(void* dst, const void* src) {
    unsigned int d = (unsigned int)__cvta_generic_to_shared(dst);
    asm volatile("cp.async.cg.shared.global [%0], [%1], 16;" :: "r"(d), "l"(src));
}
__device__ __forceinline__ void cp_commit() {
    asm volatile("cp.async.commit_group;" ::: "memory");
}
template<int N>
__device__ __forceinline__ void cp_wait() {
    asm volatile("cp.async.wait_group %0;" :: "n"(N) : "memory");
}

// ---------------------------------------------------------------------------
// tf32 tensor-core GEMM v2: BK=32, 3 smem stages (2 cp.async groups in
// flight), __launch_bounds__(256,2) -> 2 CTAs/SM (2 x 107.5 KB smem, <=128
// regs). Barriers per K halved vs BK=16; cross-CTA overlap hides them.
//   C[M,N] = A[M,K] @ B[K,N] + bias[N]  (ACT=1 -> exact GELU)
// 128x128 tile, 256 threads (8 warps 2x4), warp tile 64x32.
// smem/stage (floats): As 128*36=4608 | Bs 32*136=4352  -> 8960
// ---------------------------------------------------------------------------
#define GSTAGES 3
#define SMEM_G (GSTAGES * 8960 * 4)   /* 107520 B */

template<int ACT>
__global__ __launch_bounds__(256, 2)
void tf32_gemm(const float* __restrict__ A, const float* __restrict__ Bm,
               const float* __restrict__ bias, float* __restrict__ C,
               int M, int N, int K)
{
    extern __shared__ float smg[];
    float (*As)[128][36] = (float(*)[128][36])smg;
    float (*Bs)[32][136] = (float(*)[32][136])(smg + GSTAGES*128*36);

    const int tid  = threadIdx.x;
    const int lane = tid & 31, warp = tid >> 5;
    const int gid  = lane >> 2, tig = lane & 3;
    const int wm   = (warp & 1) << 6;
    const int wn   = (warp >> 1) << 5;
    const int m0   = blockIdx.y << 7, n0 = blockIdx.x << 7;

    // loaders: A 128 rows x 32 k (16 floats/thread), B 32 k x 128 n (16/thread)
    const int ar = tid >> 1, ac = (tid & 1) << 4;
    const int br = tid >> 3, bc = (tid & 7) << 4;

    const float* Ap = A  + (size_t)(m0 + ar) * K + ac;
    const float* Bp = Bm + (size_t)br * N + n0 + bc;

    const int nk = K >> 5;

    auto issue = [&](int s, int it) {
        const size_t ko = (size_t)it << 5;
        #pragma unroll
        for (int i = 0; i < 4; i++)
            cp_async16(&As[s][ar][ac + (i << 2)], Ap + ko + (i << 2));
        #pragma unroll
        for (int i = 0; i < 4; i++)
            cp_async16(&Bs[s][br][bc + (i << 2)], Bp + ko * N + (i << 2));
    };

    // prologue: 2 stages in flight
    issue(0, 0); cp_commit();
    issue(1, 1); cp_commit();

    float acc[4][4][4] = {};

    int buf = 0, nxt = 2;   // buffer holding iter `it`; next free buffer
    for (int it = 0; it < nk; ++it) {
        cp_wait<1>();
        __syncthreads();

        if (it + 2 < nk) issue(nxt, it + 2);
        cp_commit();

        #pragma unroll
        for (int ks = 0; ks < 32; ks += 8) {
            unsigned int af[4][4], bf[4][2];
            #pragma unroll
            for (int mi = 0; mi < 4; mi++) {
                const int m = wm + (mi << 4) + gid;
                af[mi][0] = __float_as_uint(As[buf][m    ][ks + tig]);
                af[mi][1] = __float_as_uint(As[buf][m + 8][ks + tig]);
                af[mi][2] = __float_as_uint(As[buf][m    ][ks + tig + 4]);
                af[mi][3] = __float_as_uint(As[buf][m + 8][ks + tig + 4]);
            }
            #pragma unroll
            for (int ni = 0; ni < 4; ni++) {
                const int n = wn + (ni << 3) + gid;
                bf[ni][0] = __float_as_uint(Bs[buf][ks + tig    ][n]);
                bf[ni][1] = __float_as_uint(Bs[buf][ks + tig + 4][n]);
            }
            #pragma unroll
            for (int mi = 0; mi < 4; mi++)
                #pragma unroll
                for (int ni = 0; ni < 4; ni++)
                    mma_tf32(acc[mi][ni], af[mi], bf[ni]);
        }

        buf = (buf == 2) ? 0 : buf + 1;
        nxt = (nxt == 2) ? 0 : nxt + 1;
    }

    #pragma unroll
    for (int mi = 0; mi < 4; mi++) {
        const int row = m0 + wm + (mi << 4) + gid;
        #pragma unroll
        for (int ni = 0; ni < 4; ni++) {
            const int col = n0 + wn + (ni << 3) + (tig << 1);
            float2 b2 = *(const float2*)&bias[col];
            float v0 = acc[mi][ni][0] + b2.x;
            float v1 = acc[mi][ni][1] + b2.y;
            float v2 = acc[mi][ni][2] + b2.x;
            float v3 = acc[mi][ni][3] + b2.y;
            if (ACT == 1) {
                v0 = gelu_exact(v0); v1 = gelu_exact(v1);
                v2 = gelu_exact(v2); v3 = gelu_exact(v3);
            }
            *(float2*)&C[(size_t)row * N + col]       = make_float2(v0, v1);
            *(float2*)&C[(size_t)(row + 8) * N + col] = make_float2(v2, v3);
        }
    }
}

// ---------------------------------------------------------------------------
// Fused flash-style attention (R16 config, unchanged): 512 threads, q-tile
// 256, 64-key tiles, m==0 softmax reference, natural-K layout, cp.async
// double-buffered K/V, register row sums, one final reduction.
// ---------------------------------------------------------------------------
#define QT 256
#define SMEM_FA (53504 * 4)

__global__ __launch_bounds__(512)
void attn_fused_tc(const float* __restrict__ kqv,
                   const float* __restrict__ prev,
                   float* __restrict__ energy,
                   float* __restrict__ ctx)
{
    extern __shared__ float sm[];
    float (*Qs)[68]     = (float(*)[68])sm;                  // [q][d]
    float (*Ps)[68]     = (float(*)[68])(sm + 17408);        // [q][k' 0..63]
    float (*Ks)[64][68] = (float(*)[64][68])(sm + 34816);    // [buf][k'][d]
    float (*Vs)[64][72] = (float(*)[64][72])(sm + 43520);    // [buf][k'][d]
    float* redS = sm + 52736;   // [2][256]
    float* srun = sm + 53248;   // [256]

    const int b = blockIdx.z, h = blockIdx.y, q0 = blockIdx.x << 8;
    const int tid = threadIdx.x;
    const int lane = tid & 31, warp = tid >> 5;
    const int gid = lane >> 2, tig = lane & 3;
    const int wm = (warp & 7) << 5;    // rows: 0,32,...,224 (both phases)
    const int wn = (warp >> 3) << 5;   // cols: 0,32        (both phases)
    const int ebase = (b * Hn + h) * Sn;

    const int kr = tid >> 3, dc = (tid & 7) << 3;

    auto issueKV = [&](int s, int kt2) {
        const int k0n = kt2 << 6;
        const float* krow = &kqv[(size_t)(b*Sn + k0n + kr)*TD3 + h*DHn + dc];
        cp_async16(&Ks[s][kr][dc],     krow);
        cp_async16(&Ks[s][kr][dc + 4], krow + 4);
        cp_async16(&Vs[s][kr][dc],     krow + 2*Dn);
        cp_async16(&Vs[s][kr][dc + 4], krow + 2*Dn + 4);
    };

    // Load Q tile [256][64]
    {
        const int qr = tid >> 1, qc = (tid & 1) << 5;
        const float* qrow = &kqv[(size_t)(b*Sn + q0 + qr)*TD3 + Dn + h*DHn + qc];
        #pragma unroll
        for (int i = 0; i < 8; i++)
            *(float4*)&Qs[qr][qc + (i << 2)] = *(const float4*)(qrow + (i << 2));
    }

    issueKV(0, 0); cp_commit();

    float acco[2][4][4] = {};
    float ps[4] = {0.f, 0.f, 0.f, 0.f};

    for (int kt = 0; kt < Sn/64; kt++) {
        const int k0 = kt << 6;
        const int buf = kt & 1;
        cp_wait<0>();
        __syncthreads();

        if (kt + 1 < Sn/64) issueKV(buf ^ 1, kt + 1);
        cp_commit();

        // S = Q @ K^T  (256x64, warps 8x2, warp tile 32x32)
        float acc[2][4][4] = {};
        #pragma unroll
        for (int ks = 0; ks < 64; ks += 8) {
            unsigned int af[2][4], bf[4][2];
            #pragma unroll
            for (int mi = 0; mi < 2; mi++) {
                const int m = wm + (mi << 4) + gid;
                af[mi][0] = __float_as_uint(Qs[m    ][ks + tig]);
                af[mi][1] = __float_as_uint(Qs[m + 8][ks + tig]);
                af[mi][2] = __float_as_uint(Qs[m    ][ks + tig + 4]);
                af[mi][3] = __float_as_uint(Qs[m + 8][ks + tig + 4]);
            }
            #pragma unroll
            for (int ni = 0; ni < 4; ni++) {
                const int n = wn + (ni << 3) + gid;
                bf[ni][0] = __float_as_uint(Ks[buf][n][ks + tig]);
                bf[ni][1] = __float_as_uint(Ks[buf][n][ks + tig + 4]);
            }
            #pragma unroll
            for (int mi = 0; mi < 2; mi++)
                #pragma unroll
                for (int ni = 0; ni < 4; ni++)
                    mma_tf32(acc[mi][ni], af[mi], bf[ni]);
        }

        // Epilogue: e = 0.125*s + prev -> energy; p = exp(e) -> Ps; row sums
        #pragma unroll
        for (int mi = 0; mi < 2; mi++) {
            const int rl = wm + (mi << 4) + gid;
            const size_t base0 = (size_t)(ebase + q0 + rl) * Sn + k0 + wn + (tig << 1);
            const size_t base1 = base0 + (size_t)8 * Sn;
            #pragma unroll
            for (int ni = 0; ni < 4; ni++) {
                float2 p0 = *(const float2*)&prev[base0 + (ni << 3)];
                float2 p1 = *(const float2*)&prev[base1 + (ni << 3)];
                float e00 = fmaf(acc[mi][ni][0], 0.125f, p0.x);
                float e01 = fmaf(acc[mi][ni][1], 0.125f, p0.y);
                float e10 = fmaf(acc[mi][ni][2], 0.125f, p1.x);
                float e11 = fmaf(acc[mi][ni][3], 0.125f, p1.y);
                *(float2*)&energy[base0 + (ni << 3)] = make_float2(e00, e01);
                *(float2*)&energy[base1 + (ni << 3)] = make_float2(e10, e11);
                float q00 = __expf(e00), q01 = __expf(e01);
                float q10 = __expf(e10), q11 = __expf(e11);
                ps[(mi << 1)]     += q00 + q01;
                ps[(mi << 1) + 1] += q10 + q11;
                const int col = wn + (ni << 3) + (tig << 1);
                *(float2*)&Ps[rl][col]     = make_float2(q00, q01);
                *(float2*)&Ps[rl + 8][col] = make_float2(q10, q11);
            }
        }
        __syncthreads();

        // ctx_acc += P @ V   (warps 8x2, warp tile 32x32, k-depth 64)
        #pragma unroll
        for (int ks = 0; ks < 64; ks += 8) {
            unsigned int af[2][4], bf[4][2];
            #pragma unroll
            for (int mi = 0; mi < 2; mi++) {
                const int m = wm + (mi << 4) + gid;
                af[mi][0] = __float_as_uint(Ps[m    ][ks + tig]);
                af[mi][1] = __float_as_uint(Ps[m + 8][ks + tig]);
                af[mi][2] = __float_as_uint(Ps[m    ][ks + tig + 4]);
                af[mi][3] = __float_as_uint(Ps[m + 8][ks + tig + 4]);
            }
            #pragma unroll
            for (int ni = 0; ni < 4; ni++) {
                const int n = wn + (ni << 3) + gid;
                bf[ni][0] = __float_as_uint(Vs[buf][ks + tig    ][n]);
                bf[ni][1] = __float_as_uint(Vs[buf][ks + tig + 4][n]);
            }
            #pragma unroll
            for (int mi = 0; mi < 2; mi++)
                #pragma unroll
                for (int ni = 0; ni < 4; ni++)
                    mma_tf32(acco[mi][ni], af[mi], bf[ni]);
        }
    }

    // Final row-sum reduction
    #pragma unroll
    for (int r = 0; r < 4; r++) {
        ps[r] += __shfl_xor_sync(0xffffffffu, ps[r], 1);
        ps[r] += __shfl_xor_sync(0xffffffffu, ps[r], 2);
    }
    if (tig == 0) {
        const int g = (warp >> 3) << 8;
        redS[g + wm + gid]      = ps[0];
        redS[g + wm + 8 + gid]  = ps[1];
        redS[g + wm + 16 + gid] = ps[2];
        redS[g + wm + 24 + gid] = ps[3];
    }
    __syncthreads();
    if (tid < QT) srun[tid] = redS[tid] + redS[256 + tid];
    __syncthreads();

    // Normalize and write ctx
    #pragma unroll
    for (int mi = 0; mi < 2; mi++) {
        const int rl = wm + (mi << 4) + gid;
        const float i0 = 1.0f / srun[rl];
        const float i1 = 1.0f / srun[rl + 8];
        const int row = q0 + rl;
        #pragma unroll
        for (int ni = 0; ni < 4; ni++) {
            const int col = h*DHn + wn + (ni << 3) + (tig << 1);
            *(float2*)&ctx[(size_t)(b*Sn + row)*Dn + col] =
                make_float2(acco[mi][ni][0] * i0, acco[mi][ni][1] * i0);
            *(float2*)&ctx[(size_t)(b*Sn + row + 8)*Dn + col] =
                make_float2(acco[mi][ni][2] * i1, acco[mi][ni][3] * i1);
        }
    }
}

// ---------------------------------------------------------------------------
// Fused residual + LayerNorm
// ---------------------------------------------------------------------------
__global__ __launch_bounds__(128)
void ln_kernel(const float* __restrict__ a, const float* __restrict__ b,
               const float* __restrict__ g, const float* __restrict__ beta,
               float* __restrict__ out)
{
    const int row = blockIdx.x, tid = threadIdx.x;
    const size_t base = (size_t)row * Dn + (tid << 2);

    float4 va = *(const float4*)&a[base];
    float4 vb = *(const float4*)&b[base];
    float v0 = va.x + vb.x, v1 = va.y + vb.y, v2 = va.z + vb.z, v3 = va.w + vb.w;

    float s = v0 + v1 + v2 + v3;
    float q = v0*v0 + v1*v1 + v2*v2 + v3*v3;
    #pragma unroll
    for (int o = 16; o; o >>= 1) {
        s += __shfl_xor_sync(0xffffffffu, s, o);
        q += __shfl_xor_sync(0xffffffffu, q, o);
    }
    __shared__ float ss[4], sq[4];
    const int w = tid >> 5, lane = tid & 31;
    if (!lane) { ss[w] = s; sq[w] = q; }
    __syncthreads();
    s = ss[0] + ss[1] + ss[2] + ss[3];
    q = sq[0] + sq[1] + sq[2] + sq[3];

    const float mu  = s * (1.0f / Dn);
    const float var = q * (1.0f / Dn) - mu * mu;
    const float r   = rsqrtf(var + 1e-5f);

    float4 vg = *(const float4*)&g[tid << 2];
    float4 vt = *(const float4*)&beta[tid << 2];
    float4 o4;
    o4.x = (v0 - mu) * r * vg.x + vt.x;
    o4.y = (v1 - mu) * r * vg.y + vt.y;
    o4.z = (v2 - mu) * r * vg.z + vt.z;
    o4.w = (v3 - mu) * r * vg.w + vt.w;
    *(float4*)&out[base] = o4;
}

// ---------------------------------------------------------------------------
// Launch
// ---------------------------------------------------------------------------
extern "C" void kernel_launch(void* const* d_in, const int* in_sizes, int n_in,
                              void* d_out, int out_size)
{
    (void)in_sizes; (void)n_in; (void)out_size;
    const float* x     = (const float*)d_in[0];
    const float* prev  = (const float*)d_in[1];
    const float* kqv_w = (const float*)d_in[2];
    const float* kqv_b = (const float*)d_in[3];
    const float* out_w = (const float*)d_in[4];
    const float* out_b = (const float*)d_in[5];
    const float* fc1_w = (const float*)d_in[6];
    const float* fc1_b = (const float*)d_in[7];
    const float* fc2_w = (const float*)d_in[8];
    const float* fc2_b = (const float*)d_in[9];
    const float* ln1_g = (const float*)d_in[10];
    const float* ln1_b = (const float*)d_in[11];
    const float* ln2_g = (const float*)d_in[12];
    const float* ln2_b = (const float*)d_in[13];

    float* out    = (float*)d_out;                      // [B,S,D]
    float* energy = out + (size_t)Bn * Sn * Dn;         // [B,H,S,S]

    float *kqv, *ctx, *attnout, *h, *ff, *fc1o;
    cudaGetSymbolAddress((void**)&kqv,     g_kqv);
    cudaGetSymbolAddress((void**)&ctx,     g_ctx);
    cudaGetSymbolAddress((void**)&attnout, g_attnout);
    cudaGetSymbolAddress((void**)&h,       g_h);
    cudaGetSymbolAddress((void**)&ff,      g_ff);
    cudaGetSymbolAddress((void**)&fc1o,    g_fc1);

    cudaFuncSetAttribute(tf32_gemm<0>,
                         cudaFuncAttributeMaxDynamicSharedMemorySize, SMEM_G);
    cudaFuncSetAttribute(tf32_gemm<1>,
                         cudaFuncAttributeMaxDynamicSharedMemorySize, SMEM_G);
    cudaFuncSetAttribute(attn_fused_tc,
                         cudaFuncAttributeMaxDynamicSharedMemorySize, SMEM_FA);

    // 1. kqv = x @ kqv_w + kqv_b            (tf32, BK=32, 2 CTAs/SM)
    tf32_gemm<0><<<dim3(TD3/128, NROW/128), 256, SMEM_G>>>(x, kqv_w, kqv_b, kqv, NROW, TD3, Dn);
    // 2+3. fused: energy (-> d_out) + softmax + ctx   (q-tile 256, one wave)
    attn_fused_tc<<<dim3(Sn/QT, Hn, Bn), 512, SMEM_FA>>>(kqv, prev, energy, ctx);
    // 4. attnout = ctx @ out_w + out_b
    tf32_gemm<0><<<dim3(Dn/128, NROW/128), 256, SMEM_G>>>(ctx, out_w, out_b, attnout, NROW, Dn, Dn);
    // 5. h = LN1(attnout + x)
    ln_kernel<<<NROW, 128>>>(attnout, x, ln1_g, ln1_b, h);
    // 6. fc1o = gelu(h @ fc1_w + fc1_b)
    tf32_gemm<1><<<dim3(HIDn/128, NROW/128), 256, SMEM_G>>>(h, fc1_w, fc1_b, fc1o, NROW, HIDn, Dn);
    // 7. ff = fc1o @ fc2_w + fc2_b
    tf32_gemm<0><<<dim3(Dn/128, NROW/128), 256, SMEM_G>>>(fc1o, fc2_w, fc2_b, ff, NROW, Dn, HIDn);
    // 8. out = LN2(ff + h)  -> d_out
    ln_kernel<<<NROW, 128>>>(ff, h, ln2_g, ln2_b, out);
}